// round 1
// baseline (speedup 1.0000x reference)
#include <cuda_runtime.h>
#include <cstdint>

// Problem dims
#define Bn  16
#define Cn  256
#define HWn 1024
#define Mn  16384   // B*H*W
#define Nn  8192    // codebook size
#define Kn  256     // dim

// Output layout (floats): [z_out (Mn*Kn)] [z_q (Mn*Kn)] [indices (Mn)]
#define OUT_ZQ  (Mn * Kn)
#define OUT_IDX (2 * Mn * Kn)

// Scratch (allocation-free contract: __device__ globals)
__device__ float g_wnorm[Nn];
__device__ int   g_bestidx[Mn];

// ---------------------------------------------------------------------------
// Packed fp32x2 FMA (sm_103a): 2 fp32 FMAs per instruction on the fma pipe.
// ---------------------------------------------------------------------------
#define FMA2(d, a, b) \
    asm("fma.rn.f32x2 %0, %1, %2, %0;" : "+l"(d) : "l"(a), "l"(b))
#define PACK2(d, lo, hi) \
    asm("mov.b64 %0, {%1, %2};" : "=l"(d) : "r"(lo), "r"(hi))
#define UNPACK2(lo, hi, s) \
    asm("mov.b64 {%0, %1}, %2;" : "=r"(lo), "=r"(hi) : "l"(s))

// ---------------------------------------------------------------------------
// 1) Transpose: z [B, C, HW] -> z_out [B, HW, C]  (z_out region of d_out;
//    it is also the GEMM A matrix: z_flat [Mn, Kn])
// ---------------------------------------------------------------------------
__global__ void transpose_kernel(const float* __restrict__ z,
                                 float* __restrict__ zout) {
    __shared__ float tile[32][33];
    int b   = blockIdx.z;
    int hw0 = blockIdx.x * 32;
    int c0  = blockIdx.y * 32;
    const float* zp = z    + (size_t)b * (Cn * HWn);
    float*       op = zout + (size_t)b * (Cn * HWn);
    int tx = threadIdx.x, ty = threadIdx.y;  // 32 x 8
#pragma unroll
    for (int j = 0; j < 32; j += 8)
        tile[ty + j][tx] = zp[(c0 + ty + j) * HWn + hw0 + tx];
    __syncthreads();
#pragma unroll
    for (int j = 0; j < 32; j += 8)
        op[(hw0 + ty + j) * Cn + c0 + tx] = tile[tx][ty + j];
}

// ---------------------------------------------------------------------------
// 2) wnorm[n] = 0.5 * ||w_n||^2   (one warp per codebook row)
// ---------------------------------------------------------------------------
__global__ void wnorm_kernel(const float* __restrict__ w) {
    int gwarp = (blockIdx.x * blockDim.x + threadIdx.x) >> 5;
    int lane  = threadIdx.x & 31;
    if (gwarp >= Nn) return;
    const float* wr = w + (size_t)gwarp * Kn;
    float s = 0.f;
#pragma unroll
    for (int i = 0; i < Kn / 32; i++) {
        float v = wr[lane + i * 32];
        s += v * v;
    }
#pragma unroll
    for (int o = 16; o > 0; o >>= 1) s += __shfl_xor_sync(0xffffffffu, s, o);
    if (lane == 0) g_wnorm[gwarp] = 0.5f * s;
}

// ---------------------------------------------------------------------------
// 3) GEMM + argmax:  score[m,n] = dot(z_m, w_n) - 0.5||w_n||^2
//    argmin_n d  ==  argmax_n score, ties -> smallest n (JAX argmin semantics)
//    BM=BN=128, BK=16, 256 threads, 8x8 microtile, FFMA2-packed along n.
// ---------------------------------------------------------------------------
#define BM 128
#define BN 128
#define BK 16
#define TM 8
#define TN 8

__global__ __launch_bounds__(256)
void gemm_argmax_kernel(const float* __restrict__ A,   // z_flat [Mn, Kn]
                        const float* __restrict__ Wt,  // weight [Nn, Kn]
                        float* __restrict__ idx_out) { // indices as float
    __shared__ float As[BK][BM + 1];
    __shared__ float Bs[BK][BN + 1];
    __shared__ float swn[BN];
    __shared__ float sval[16][BM];
    __shared__ int   sidx[16][BM];

    const int tid = threadIdx.x;
    const int tx  = tid & 15;   // column group
    const int ty  = tid >> 4;   // row group
    const int m0  = blockIdx.x * BM;

    float bestv[TM];
    int   besti[TM];
#pragma unroll
    for (int i = 0; i < TM; i++) { bestv[i] = -3.4e38f; besti[i] = 0; }

    for (int n0 = 0; n0 < Nn; n0 += BN) {
        __syncthreads();  // prior n-tile's reads of swn/As/Bs complete
        if (tid < BN) swn[tid] = g_wnorm[n0 + tid];

        unsigned long long acc2[TM][TN / 2];
#pragma unroll
        for (int i = 0; i < TM; i++)
#pragma unroll
            for (int q = 0; q < TN / 2; q++) acc2[i][q] = 0ull;

        for (int k0 = 0; k0 < Kn; k0 += BK) {
            // stage load: 2048 floats each tile = 512 float4, 2 per thread
#pragma unroll
            for (int l = 0; l < 2; l++) {
                int f  = tid + l * 256;
                int m  = f >> 2;
                int kq = (f & 3) * 4;
                float4 v = *reinterpret_cast<const float4*>(
                    &A[(size_t)(m0 + m) * Kn + k0 + kq]);
                As[kq + 0][m] = v.x; As[kq + 1][m] = v.y;
                As[kq + 2][m] = v.z; As[kq + 3][m] = v.w;
            }
#pragma unroll
            for (int l = 0; l < 2; l++) {
                int f  = tid + l * 256;
                int n  = f >> 2;
                int kq = (f & 3) * 4;
                float4 v = *reinterpret_cast<const float4*>(
                    &Wt[(size_t)(n0 + n) * Kn + k0 + kq]);
                Bs[kq + 0][n] = v.x; Bs[kq + 1][n] = v.y;
                Bs[kq + 2][n] = v.z; Bs[kq + 3][n] = v.w;
            }
            __syncthreads();  // tiles (and swn on first stage) visible

#pragma unroll
            for (int k = 0; k < BK; k++) {
                float a[TM], bb[TN];
#pragma unroll
                for (int i = 0; i < TM; i++) a[i] = As[k][ty + i * 16];
#pragma unroll
                for (int j = 0; j < TN; j++) bb[j] = Bs[k][tx + j * 16];

                unsigned long long ap[TM], bp[TN / 2];
#pragma unroll
                for (int i = 0; i < TM; i++) {
                    unsigned int u = __float_as_uint(a[i]);
                    PACK2(ap[i], u, u);
                }
#pragma unroll
                for (int q = 0; q < TN / 2; q++) {
                    PACK2(bp[q], __float_as_uint(bb[2 * q]),
                                 __float_as_uint(bb[2 * q + 1]));
                }
#pragma unroll
                for (int i = 0; i < TM; i++)
#pragma unroll
                    for (int q = 0; q < TN / 2; q++)
                        FMA2(acc2[i][q], ap[i], bp[q]);
            }
            __syncthreads();  // compute done before next stage overwrite
        }

        // fold in -0.5||w||^2 and update running argmax (n ascending, strict >)
#pragma unroll
        for (int i = 0; i < TM; i++) {
#pragma unroll
            for (int q = 0; q < TN / 2; q++) {
                unsigned int u0, u1;
                UNPACK2(u0, u1, acc2[i][q]);
                int c0 = tx + (2 * q) * 16;
                int c1 = tx + (2 * q + 1) * 16;
                float s0 = __uint_as_float(u0) - swn[c0];
                float s1 = __uint_as_float(u1) - swn[c1];
                if (s0 > bestv[i]) { bestv[i] = s0; besti[i] = n0 + c0; }
                if (s1 > bestv[i]) { bestv[i] = s1; besti[i] = n0 + c1; }
            }
        }
    }

    // cross-thread reduction over the 16 column groups (tx) per row
#pragma unroll
    for (int i = 0; i < TM; i++) {
        sval[tx][ty + i * 16] = bestv[i];
        sidx[tx][ty + i * 16] = besti[i];
    }
    __syncthreads();
    if (tid < BM) {
        float bv = sval[0][tid];
        int   bi = sidx[0][tid];
#pragma unroll
        for (int t = 1; t < 16; t++) {
            float v  = sval[t][tid];
            int   ii = sidx[t][tid];
            if (v > bv || (v == bv && ii < bi)) { bv = v; bi = ii; }
        }
        int m = m0 + tid;
        g_bestidx[m] = bi;
        idx_out[m]   = (float)bi;
    }
}

// ---------------------------------------------------------------------------
// 4) Gather: z_q[m, :] = weight[bestidx[m], :]   (float4 per thread)
// ---------------------------------------------------------------------------
__global__ void gather_kernel(const float* __restrict__ w,
                              float* __restrict__ zq) {
    int t   = blockIdx.x * blockDim.x + threadIdx.x;  // float4 index
    int row = t >> 6;                                  // Kn/4 = 64 f4 per row
    int c   = t & 63;
    int idx = g_bestidx[row];
    reinterpret_cast<float4*>(zq)[t] =
        reinterpret_cast<const float4*>(w)[(size_t)idx * 64 + c];
}

// ---------------------------------------------------------------------------
extern "C" void kernel_launch(void* const* d_in, const int* in_sizes, int n_in,
                              void* d_out, int out_size) {
    const float* z = (const float*)d_in[0];   // [16,256,32,32]
    const float* w = (const float*)d_in[1];   // [8192,256]
    float* out   = (float*)d_out;
    float* z_out = out;            // doubles as GEMM A (z_flat [Mn,Kn])
    float* z_q   = out + OUT_ZQ;
    float* idxf  = out + OUT_IDX;

    dim3 tt(32, 8);
    transpose_kernel<<<dim3(HWn / 32, Cn / 32, Bn), tt>>>(z, z_out);
    wnorm_kernel<<<Nn / 8, 256>>>(w);
    gemm_argmax_kernel<<<Mn / BM, 256>>>(z_out, w, idxf);
    gather_kernel<<<(Mn * Kn / 4) / 256, 256>>>(w, z_q);
}

// round 4
// speedup vs baseline: 1.7429x; 1.7429x over previous
#include <cuda_runtime.h>
#include <cuda_bf16.h>
#include <cstdint>

// ---------------------------------------------------------------------------
#define Mn  16384
#define Nn  8192
#define Kn  256
#define HWn 1024
#define Bln 16

#define OUT_ZQ  (Mn * Kn)
#define OUT_IDX (2 * Mn * Kn)

#define CERT_WINDOW 1.0f   // ~11 sigma of bf16-dot error; flags ~2% of rows

// ---------------------------------------------------------------------------
// Device scratch (allocation-free contract)
// ---------------------------------------------------------------------------
__device__ __align__(16) __nv_bfloat16 g_zb[Mn * Kn];
__device__ __align__(16) __nv_bfloat16 g_wb[Nn * Kn];
__device__ float g_wnorm[Nn];
__device__ int   g_bestidx[Mn];
__device__ int   g_cand[Mn][4];
__device__ int   g_flag[Mn];
__device__ int   g_flag_list[Mn];
__device__ int   g_flag_count;

// ---------------------------------------------------------------------------
__device__ __forceinline__ uint32_t smem_u32(const void* p) {
    uint32_t a;
    asm("{ .reg .u64 t; cvta.to.shared.u64 t, %1; cvt.u32.u64 %0, t; }"
        : "=r"(a) : "l"(p));
    return a;
}
__device__ __forceinline__ void cp_async16(uint32_t dst, const void* src) {
    asm volatile("cp.async.cg.shared.global [%0], [%1], 16;"
                 :: "r"(dst), "l"(src) : "memory");
}
#define CP_COMMIT() asm volatile("cp.async.commit_group;" ::: "memory")
#define CP_WAIT0()  asm volatile("cp.async.wait_group 0;" ::: "memory")

// non-transposed ldmatrix: correct for A [m][k] row-major AND B [n][k] row-major
// (mma row.col: B col-major k x n == row-major [n][k])
#define LDSM_X4(r0, r1, r2, r3, a) \
    asm volatile("ldmatrix.sync.aligned.m8n8.x4.shared.b16 {%0,%1,%2,%3}, [%4];" \
                 : "=r"(r0), "=r"(r1), "=r"(r2), "=r"(r3) : "r"(a))

#define MMA16816(c, a, b) \
    asm volatile("mma.sync.aligned.m16n8k16.row.col.f32.bf16.bf16.f32 " \
                 "{%0,%1,%2,%3}, {%4,%5,%6,%7}, {%8,%9}, {%0,%1,%2,%3};" \
                 : "+f"((c)[0]), "+f"((c)[1]), "+f"((c)[2]), "+f"((c)[3]) \
                 : "r"((a)[0]), "r"((a)[1]), "r"((a)[2]), "r"((a)[3]), \
                   "r"((b)[0]), "r"((b)[1]))

// ---------------------------------------------------------------------------
// 1) Transpose + bf16 convert: z [B,C,HW] -> z_out fp32 [B,HW,C] + g_zb bf16
// ---------------------------------------------------------------------------
__global__ void transpose_kernel(const float* __restrict__ z,
                                 float* __restrict__ zout) {
    __shared__ float tile[32][33];
    int b   = blockIdx.z;
    int hw0 = blockIdx.x * 32;
    int c0  = blockIdx.y * 32;
    const float* zp = z + (size_t)b * (Kn * HWn);
    size_t obase    = (size_t)b * (Kn * HWn);
    int tx = threadIdx.x, ty = threadIdx.y;
#pragma unroll
    for (int j = 0; j < 32; j += 8)
        tile[ty + j][tx] = zp[(c0 + ty + j) * HWn + hw0 + tx];
    __syncthreads();
#pragma unroll
    for (int j = 0; j < 32; j += 8) {
        float v = tile[tx][ty + j];
        size_t o = obase + (size_t)(hw0 + ty + j) * Kn + c0 + tx;
        zout[o] = v;
        g_zb[o] = __float2bfloat16(v);
    }
}

// ---------------------------------------------------------------------------
// 2) W bf16 convert + 0.5||w||^2
// ---------------------------------------------------------------------------
__global__ void wconvert_kernel(const float* __restrict__ w) {
    if (blockIdx.x == 0 && threadIdx.x == 0) g_flag_count = 0;
    int gwarp = (blockIdx.x * blockDim.x + threadIdx.x) >> 5;
    int lane  = threadIdx.x & 31;
    if (gwarp >= Nn) return;
    const float* wr = w + (size_t)gwarp * Kn;
    float s = 0.f;
#pragma unroll
    for (int i = 0; i < Kn / 32; i++) {
        float v = wr[lane + i * 32];
        s += v * v;
        g_wb[(size_t)gwarp * Kn + lane + i * 32] = __float2bfloat16(v);
    }
#pragma unroll
    for (int o = 16; o > 0; o >>= 1) s += __shfl_xor_sync(0xffffffffu, s, o);
    if (lane == 0) g_wnorm[gwarp] = 0.5f * s;
}

// ---------------------------------------------------------------------------
// 3) bf16 mma.sync GEMM + per-row top-4
//    BM=128 per CTA, 8 warps in 4(m) x 2(n), warp tile 32x64, K=256 in SMEM.
// ---------------------------------------------------------------------------
#define SM_A   0          // 64 KB
#define SM_B0  65536      // 64 KB
#define SM_B1  131072     // 64 KB
#define SM_WN  196608     // 32 KB
#define SMEM_BYTES 229376
#define SM_MV  65536      // merge val  (reuses B0)
#define SM_MI  81920      // merge idx

// swizzled byte offset within a 512B (256 bf16) row: chunk c (0..31), row m
#define ROWSWZ(m, c) ((uint32_t)((m) * 512 + ((((c)) ^ ((m) & 7)) << 4)))

__global__ void __launch_bounds__(256, 1) gemm_kernel() {
    extern __shared__ char smem[];
    const uint32_t sbase = smem_u32(smem);
    const int tid  = threadIdx.x;
    const int lane = tid & 31;
    const int wid  = tid >> 5;
    const int wm   = wid >> 1;     // 0..3  (m position)
    const int wn   = wid & 1;      // 0..1  (n position)
    const int lj   = lane >> 3;    // ldmatrix quad
    const int lr   = lane & 7;
    const int m0   = blockIdx.x * 128;

    // stage wnorm into SMEM
    float* swn = (float*)(smem + SM_WN);
    for (int i = tid; i < Nn; i += 256) swn[i] = g_wnorm[i];

    // A tile (128 x 256 bf16) via cp.async, swizzled
    {
        const char* src = (const char*)g_zb + (size_t)m0 * 512;
#pragma unroll
        for (int i = 0; i < 16; i++) {
            int f = tid + i * 256;
            int m = f >> 5, c = f & 31;
            cp_async16(sbase + SM_A + ROWSWZ(m, c), src + (size_t)m * 512 + c * 16);
        }
    }
    // B tile 0
    {
        const char* src = (const char*)g_wb;
#pragma unroll
        for (int i = 0; i < 16; i++) {
            int f = tid + i * 256;
            int n = f >> 5, c = f & 31;
            cp_async16(sbase + SM_B0 + ROWSWZ(n, c), src + (size_t)n * 512 + c * 16);
        }
    }
    CP_COMMIT();
    CP_WAIT0();
    __syncthreads();

    // per-lane ldmatrix row constants
    // A matrices: m0=(r0-7,k0-7) m1=(r8-15,k0-7) m2=(r0-7,k8-15) m3=(r8-15,k8-15)
    uint32_t aBase[2], aSwz[2];
#pragma unroll
    for (int mt = 0; mt < 2; mt++) {
        int ml = wm * 32 + mt * 16 + ((lj & 1) << 3) + lr;
        aBase[mt] = sbase + SM_A + (uint32_t)ml * 512;
        aSwz[mt]  = (uint32_t)(ml & 7);
    }
    // B matrices: m0=(n0-7,k0-7) m1=(n0-7,k8-15) m2=(n8-15,k0-7) m3=(n8-15,k8-15)
    uint32_t bBase[4], bSwz[4];
#pragma unroll
    for (int p = 0; p < 4; p++) {
        int nl = wn * 64 + p * 16 + ((lj >> 1) << 3) + lr;
        bBase[p] = (uint32_t)nl * 512;
        bSwz[p]  = (uint32_t)(nl & 7);
    }

    // running top-4 per owned row (slot = mt*2 + half)
    float bv[4][4];
    int   bi[4][4];
#pragma unroll
    for (int s = 0; s < 4; s++)
#pragma unroll
        for (int e = 0; e < 4; e++) { bv[s][e] = -3.4e38f; bi[s][e] = 0; }

#define TOP4_INS(S, VAL, IDX)                                              \
    if ((VAL) > bv[S][3]) {                                                \
        float _cv = (VAL); int _ci = (IDX);                                \
        _Pragma("unroll")                                                  \
        for (int _q = 0; _q < 4; _q++) {                                   \
            if (_cv > bv[S][_q]) {                                         \
                float _tv = bv[S][_q]; int _ti = bi[S][_q];                \
                bv[S][_q] = _cv; bi[S][_q] = _ci; _cv = _tv; _ci = _ti;    \
            }                                                              \
        }                                                                  \
    }

    int buf = 0;
    for (int t = 0; t < 64; t++) {
        const uint32_t cur = sbase + (buf ? SM_B1 : SM_B0);
        if (t < 63) {
            const uint32_t nxt = sbase + (buf ? SM_B0 : SM_B1);
            const char* src = (const char*)g_wb + (size_t)(t + 1) * 128 * 512;
#pragma unroll
            for (int i = 0; i < 16; i++) {
                int f = tid + i * 256;
                int n = f >> 5, c = f & 31;
                cp_async16(nxt + ROWSWZ(n, c), src + (size_t)n * 512 + c * 16);
            }
            CP_COMMIT();
        }

        float C[2][8][4];
#pragma unroll
        for (int mt = 0; mt < 2; mt++)
#pragma unroll
            for (int f = 0; f < 8; f++)
#pragma unroll
                for (int e = 0; e < 4; e++) C[mt][f][e] = 0.f;

#pragma unroll
        for (int ks = 0; ks < 16; ks++) {
            uint32_t a[2][4];
#pragma unroll
            for (int mt = 0; mt < 2; mt++) {
                uint32_t cA = (uint32_t)(ks * 2 + (lj >> 1));
                uint32_t ad = aBase[mt] + (((cA ^ aSwz[mt])) << 4);
                LDSM_X4(a[mt][0], a[mt][1], a[mt][2], a[mt][3], ad);
            }
            uint32_t b[8][2];
#pragma unroll
            for (int p = 0; p < 4; p++) {
                uint32_t cB = (uint32_t)(ks * 2 + (lj & 1));
                uint32_t bd = cur + bBase[p] + (((cB ^ bSwz[p])) << 4);
                // non-trans: fragments land as {n0-7:k-even, n0-7:k-odd,
                //                               n8-15:k-even, n8-15:k-odd}
                LDSM_X4(b[2 * p][0], b[2 * p][1], b[2 * p + 1][0], b[2 * p + 1][1], bd);
            }
#pragma unroll
            for (int mt = 0; mt < 2; mt++)
#pragma unroll
                for (int f = 0; f < 8; f++)
                    MMA16816(C[mt][f], a[mt], b[f]);
        }

        // epilogue: score = acc - 0.5||w||^2, update top-4
        {
            int cbase = t * 128 + wn * 64 + 2 * (lane & 3);
            float sw[8][2];
#pragma unroll
            for (int f = 0; f < 8; f++) {
                sw[f][0] = swn[cbase + f * 8 + 0];
                sw[f][1] = swn[cbase + f * 8 + 1];
            }
#pragma unroll
            for (int mt = 0; mt < 2; mt++) {
#pragma unroll
                for (int f = 0; f < 8; f++) {
#pragma unroll
                    for (int e = 0; e < 2; e++) {
                        int col = cbase + f * 8 + e;
                        float s0 = C[mt][f][e]     - sw[f][e];  // row g
                        float s1 = C[mt][f][2 + e] - sw[f][e];  // row g+8
                        TOP4_INS(mt * 2 + 0, s0, col);
                        TOP4_INS(mt * 2 + 1, s1, col);
                    }
                }
            }
        }

        if (t < 63) CP_WAIT0();
        __syncthreads();
        buf ^= 1;
    }

    // ---- cross-thread merge via SMEM (reuse B0 region) ----
    float* MV = (float*)(smem + SM_MV);   // [128][32]
    int*   MI = (int*)  (smem + SM_MI);   // [128][32]
#pragma unroll
    for (int s = 0; s < 4; s++) {
        int row = wm * 32 + (s >> 1) * 16 + (s & 1) * 8 + (lane >> 2);
        int col = wn * 16 + (lane & 3) * 4;
#pragma unroll
        for (int e = 0; e < 4; e++) {
            MV[row * 32 + col + e] = bv[s][e];
            MI[row * 32 + col + e] = bi[s][e];
        }
    }
    __syncthreads();

    if (tid < 128) {
        int row = tid;
        float tv[4] = {-3.4e38f, -3.4e38f, -3.4e38f, -3.4e38f};
        int   ti[4] = {0, 0, 0, 0};
#pragma unroll
        for (int k = 0; k < 32; k++) {
            float v = MV[row * 32 + k];
            int   ix = MI[row * 32 + k];
            if (v > tv[3]) {
                float cv = v; int ci = ix;
#pragma unroll
                for (int q = 0; q < 4; q++) {
                    if (cv > tv[q]) {
                        float xv = tv[q]; int xi = ti[q];
                        tv[q] = cv; ti[q] = ci; cv = xv; ci = xi;
                    }
                }
            }
        }
        int m = m0 + row;
#pragma unroll
        for (int e = 0; e < 4; e++) g_cand[m][e] = ti[e];
        int fl = (tv[0] - tv[3] <= CERT_WINDOW) ? 1 : 0;
        g_flag[m] = fl;
        if (fl) {
            int p = atomicAdd(&g_flag_count, 1);
            g_flag_list[p] = m;
        }
    }
}

// ---------------------------------------------------------------------------
// 4) Exact fp32 rescore of top-4 candidates (one warp per row)
// ---------------------------------------------------------------------------
__global__ __launch_bounds__(256) void rescore_kernel(const float* __restrict__ zout,
                                                      const float* __restrict__ w,
                                                      float* __restrict__ idxf) {
    int m    = (blockIdx.x * blockDim.x + threadIdx.x) >> 5;
    int lane = threadIdx.x & 31;
    if (m >= Mn) return;
    if (g_flag[m]) return;

    float zr[8];
    const float* zp = zout + (size_t)m * Kn;
#pragma unroll
    for (int j = 0; j < 8; j++) zr[j] = zp[lane + 32 * j];

    float bestS = -3.4e38f;
    int   bestI = 0x7fffffff;
#pragma unroll
    for (int c = 0; c < 4; c++) {
        int idx = g_cand[m][c];
        const float* wp = w + (size_t)idx * Kn;
        float s = 0.f;
#pragma unroll
        for (int j = 0; j < 8; j++) s += zr[j] * wp[lane + 32 * j];
#pragma unroll
        for (int o = 16; o > 0; o >>= 1) s += __shfl_xor_sync(0xffffffffu, s, o);
        s -= g_wnorm[idx];
        if (s > bestS || (s == bestS && idx < bestI)) { bestS = s; bestI = idx; }
    }
    if (lane == 0) {
        g_bestidx[m] = bestI;
        idxf[m] = (float)bestI;
    }
}

// ---------------------------------------------------------------------------
// 5) Fallback full exact scan for flagged rows
// ---------------------------------------------------------------------------
__global__ __launch_bounds__(256) void fallback_kernel(const float* __restrict__ zout,
                                                       const float* __restrict__ w,
                                                       float* __restrict__ idxf) {
    __shared__ float sv[8];
    __shared__ int   si[8];
    int nflag = g_flag_count;
    int wi = threadIdx.x >> 5, lane = threadIdx.x & 31;
    for (int r = blockIdx.x; r < nflag; r += gridDim.x) {
        int m = g_flag_list[r];
        float zr[8];
        const float* zp = zout + (size_t)m * Kn;
#pragma unroll
        for (int j = 0; j < 8; j++) zr[j] = zp[lane + 32 * j];
        float bS = -3.4e38f;
        int   bI = 0x7fffffff;
        for (int n = wi; n < Nn; n += 8) {
            const float* wp = w + (size_t)n * Kn;
            float s = 0.f;
#pragma unroll
            for (int j = 0; j < 8; j++) s += zr[j] * wp[lane + 32 * j];
#pragma unroll
            for (int o = 16; o > 0; o >>= 1) s += __shfl_xor_sync(0xffffffffu, s, o);
            s -= g_wnorm[n];
            if (s > bS || (s == bS && n < bI)) { bS = s; bI = n; }
        }
        if (lane == 0) { sv[wi] = bS; si[wi] = bI; }
        __syncthreads();
        if (threadIdx.x == 0) {
            float bvv = sv[0]; int bii = si[0];
#pragma unroll
            for (int q = 1; q < 8; q++) {
                if (sv[q] > bvv || (sv[q] == bvv && si[q] < bii)) { bvv = sv[q]; bii = si[q]; }
            }
            g_bestidx[m] = bii;
            idxf[m] = (float)bii;
        }
        __syncthreads();
    }
}

// ---------------------------------------------------------------------------
// 6) Gather z_q
// ---------------------------------------------------------------------------
__global__ void gather_kernel(const float* __restrict__ w,
                              float* __restrict__ zq) {
    int t   = blockIdx.x * blockDim.x + threadIdx.x;
    int row = t >> 6;
    int c   = t & 63;
    int idx = g_bestidx[row];
    reinterpret_cast<float4*>(zq)[t] =
        reinterpret_cast<const float4*>(w)[(size_t)idx * 64 + c];
}

// ---------------------------------------------------------------------------
extern "C" void kernel_launch(void* const* d_in, const int* in_sizes, int n_in,
                              void* d_out, int out_size) {
    const float* z = (const float*)d_in[0];
    const float* w = (const float*)d_in[1];
    float* out   = (float*)d_out;
    float* z_out = out;
    float* z_q   = out + OUT_ZQ;
    float* idxf  = out + OUT_IDX;

    cudaFuncSetAttribute(gemm_kernel,
                         cudaFuncAttributeMaxDynamicSharedMemorySize, SMEM_BYTES);

    dim3 tt(32, 8);
    transpose_kernel<<<dim3(HWn / 32, Kn / 32, Bln), tt>>>(z, z_out);
    wconvert_kernel<<<Nn / 8, 256>>>(w);
    gemm_kernel<<<Mn / 128, 256, SMEM_BYTES>>>();
    rescore_kernel<<<Mn / 8, 256>>>(z_out, w, idxf);
    fallback_kernel<<<128, 256>>>(z_out, w, idxf);
    gather_kernel<<<(Mn * Kn / 4) / 256, 256>>>(w, z_q);
}